// round 15
// baseline (speedup 1.0000x reference)
#include <cuda_runtime.h>
#include <cuda_fp16.h>
#include <cstdint>

#define N_ROWS 32768
#define N_CODES 8192
#define DIM 64
#define HW 4096
#define ZB 262144
#define NELEM 2097152
#define CHC 64               // codes per chunk
#define NCHL 64              // chunks per CTA (one code half = 4096 codes)
#define CAP (1 << 22)
#define HMARGIN 4.5e-4f

__device__ float              g_A[N_ROWS];
__device__ float              g_B[N_CODES];
__device__ float              g_zT[N_ROWS * DIM];
__device__ __half             g_zh[N_ROWS * DIM];
__device__ __half             g_eh[N_CODES * DIM];
__device__ unsigned long long g_key[N_ROWS];
__device__ unsigned int       g_rowmax[N_ROWS];       // order-encoded float max dot
__device__ unsigned long long g_cand[CAP];            // [dot_f16:16]<<32 | [row:15|j:13]
__device__ int                g_cnt;
__device__ double             g_partial[2048];

__device__ __forceinline__ uint32_t smem_u32(const void* p) {
    uint32_t a;
    asm("{ .reg .u64 t; cvta.to.shared.u64 t, %1; cvt.u32.u64 %0, t; }" : "=r"(a) : "l"(p));
    return a;
}
__device__ __forceinline__ void cp_async16(uint32_t dst, const void* src) {
    asm volatile("cp.async.cg.shared.global [%0], [%1], 16;" :: "r"(dst), "l"(src) : "memory");
}
#define CP_COMMIT() asm volatile("cp.async.commit_group;" ::: "memory")
#define CP_WAIT1()  asm volatile("cp.async.wait_group 1;" ::: "memory")
#define CP_WAIT0()  asm volatile("cp.async.wait_group 0;" ::: "memory")

__device__ __forceinline__ void mma16816h(uint32_t& c0, uint32_t& c1,
                                          uint32_t a0, uint32_t a1, uint32_t a2, uint32_t a3,
                                          uint32_t b0, uint32_t b1) {
    asm volatile(
        "mma.sync.aligned.m16n8k16.row.col.f16.f16.f16.f16 "
        "{%0,%1}, {%2,%3,%4,%5}, {%6,%7}, {%0,%1};"
        : "+r"(c0), "+r"(c1)
        : "r"(a0), "r"(a1), "r"(a2), "r"(a3), "r"(b0), "r"(b1));
}
__device__ __forceinline__ void ldmatrix_x4(uint32_t& r0, uint32_t& r1, uint32_t& r2,
                                            uint32_t& r3, uint32_t addr) {
    asm volatile("ldmatrix.sync.aligned.m8n8.x4.shared.b16 {%0,%1,%2,%3}, [%4];"
                 : "=r"(r0), "=r"(r1), "=r"(r2), "=r"(r3) : "r"(addr));
}
__device__ __forceinline__ __half2 u2h(uint32_t v) {
    return reinterpret_cast<__half2&>(v);
}
// monotone float -> unsigned encoding (for atomicMax)
__device__ __forceinline__ unsigned fenc(float f) {
    int b = __float_as_int(f);
    return (b >= 0) ? ((unsigned)b | 0x80000000u) : ~(unsigned)b;
}
__device__ __forceinline__ float fdec(unsigned e) {
    int b = (e & 0x80000000u) ? (int)(e ^ 0x80000000u) : (int)~e;
    return __int_as_float(b);
}
__device__ __forceinline__ unsigned long long pkcand(int row, int j, uint32_t hbits) {
    return ((unsigned long long)hbits << 32) |
           (unsigned long long)(((unsigned)row << 13) | (unsigned)j);
}

// ---------------------------------------------------------------------------
// Transpose z -> zT (f32 row-major), zh (fp16), A = ||z||^2 (ascending-c fma)
// ---------------------------------------------------------------------------
__global__ void vq_transpose(const float* __restrict__ z) {
    __shared__ float sm[64][65];
    int b = blockIdx.x >> 6;
    int hw0 = (blockIdx.x & 63) << 6;
    int cc = threadIdx.x >> 6, hh = threadIdx.x & 63;
    const float* zb = z + b * ZB + hw0;
#pragma unroll
    for (int cq = 0; cq < 16; cq++) {
        int c = cq * 4 + cc;
        sm[hh][c] = zb[c * HW + hh];
    }
    __syncthreads();
#pragma unroll
    for (int rq = 0; rq < 16; rq++) {
        int r = rq * 4 + cc;
        int n = b * 4096 + hw0 + r;
        float v = sm[r][hh];
        g_zT[n * DIM + hh] = v;
        g_zh[n * DIM + hh] = __float2half(v);
    }
    if (threadIdx.x < 64) {
        int r = threadIdx.x;
        float s = 0.f;
#pragma unroll
        for (int c = 0; c < DIM; c++) s = __fmaf_rn(sm[r][c], sm[r][c], s);
        g_A[b * 4096 + hw0 + r] = s;
    }
}

__global__ void vq_prep(const float* __restrict__ emb) {
    int t = blockIdx.x * blockDim.x + threadIdx.x;
    if (t < N_CODES * DIM) g_eh[t] = __float2half(emb[t]);
    if (t < N_ROWS) {
        g_key[t] = 0xFFFFFFFFFFFFFFFFull;
        g_rowmax[t] = 0u;
    }
    if (t == 0) g_cnt = 0;
    if (t < N_CODES) {
        const float4* ep = (const float4*)(emb + t * DIM);
        float s = 0.f;
#pragma unroll
        for (int i = 0; i < 16; i++) {
            float4 v = ep[i];
            s = __fmaf_rn(v.x, v.x, s);
            s = __fmaf_rn(v.y, v.y, s);
            s = __fmaf_rn(v.z, v.z, s);
            s = __fmaf_rn(v.w, v.w, s);
        }
        g_B[t] = s;
    }
}

// no-op spacer so vq_mma lands in the ncu-captured (4th) launch slot
__global__ void vq_probe(void) {}

// ---------------------------------------------------------------------------
// Filter: fp16 mma.sync + per-(row,code-half) running max.
// 128 thr / 4 warps / 64 rows x 4096 codes, grid 1024 (~6.9 CTAs/SM).
// Emission: smem-staged accs + ffs loop (cheap) with fp16-dot payload;
// per-row FINAL max via atomicMax lets vq_exact drop stale candidates.
// ---------------------------------------------------------------------------
#define SMEM_STAGE (3 * CHC * 128)          // staging after the 3 e buffers
#define SMEM_MMA   (SMEM_STAGE + 16 * 512)  // 24KB buffers + 8KB staging

__global__ __launch_bounds__(128, 7) void vq_mma(void) {
    extern __shared__ char smc[];
    uint32_t sb = smem_u32(smc);
    int tid = threadIdx.x;
    int lane = tid & 31;
    int wid = tid >> 5;                   // 4 warps
    int row0 = (blockIdx.x >> 1) * 64;
    int cbase = (blockIdx.x & 1) * NCHL;  // code half: global chunk offset
    int g = lane >> 2, q = lane & 3;

    int rw = row0 + wid * 16;
    int row_a = rw + g, row_b = row_a + 8;
    uint32_t a[4][4];
#pragma unroll
    for (int ks = 0; ks < 4; ks++) {
        const char* pa = (const char*)(g_zh + row_a * DIM + ks * 16 + q * 2);
        const char* pb = (const char*)(g_zh + row_b * DIM + ks * 16 + q * 2);
        a[ks][0] = *(const uint32_t*)pa;
        a[ks][1] = *(const uint32_t*)pb;
        a[ks][2] = *(const uint32_t*)(pa + 16);
        a[ks][3] = *(const uint32_t*)(pb + 16);
    }

    uint32_t r8 = (uint32_t)(lane & 7);
    uint32_t h2 = (uint32_t)(lane >> 3);
    uint32_t seg1 = (h2 ^ r8) * 16;
    uint32_t seg2 = ((4 + h2) ^ r8) * 16;
    uint32_t lrow = r8 * 128;
    uint32_t stg = sb + SMEM_STAGE + (uint32_t)tid * 4;

    // prefetch chunks 0,1 (512 16B segs each; 128 thr x 4)
#pragma unroll
    for (int pc = 0; pc < 2; pc++) {
#pragma unroll
        for (int i = 0; i < 4; i++) {
            int s = tid + i * 128;
            int r = s >> 3, seg = s & 7;
            uint32_t off = (uint32_t)(r * 128 + seg * 16);
            uint32_t dst = sb + pc * 8192 + (off ^ ((off >> 3) & 0x70));
            cp_async16(dst, g_eh + ((cbase + pc) * CHC + r) * DIM + seg * 8);
        }
        CP_COMMIT();
    }

    const float NEGINF = -__int_as_float(0x7f800000);
    float run0 = NEGINF, run1 = NEGINF;

    int buf = 0;                 // buf = c % 3
    for (int c = 0; c < NCHL; c++) {
        if (c < NCHL - 1) CP_WAIT1(); else CP_WAIT0();
        __syncthreads();         // chunk c ready; chunk c-1's buffer now free

        uint32_t ebase = sb + (uint32_t)buf * 8192 + lrow;

        // prefetch c+2 into buffer (c+2)%3 == (c-1)%3
        if (c + 2 < NCHL) {
            int pbuf = buf - 1; if (pbuf < 0) pbuf = 2;
#pragma unroll
            for (int i = 0; i < 4; i++) {
                int s = tid + i * 128;
                int r = s >> 3, seg = s & 7;
                uint32_t off = (uint32_t)(r * 128 + seg * 16);
                uint32_t dst = sb + (uint32_t)pbuf * 8192 + (off ^ ((off >> 3) & 0x70));
                cp_async16(dst, g_eh + ((cbase + c + 2) * CHC + r) * DIM + seg * 8);
            }
            CP_COMMIT();
        }

        __half2 acc_a[8], acc_b[8];
#pragma unroll
        for (int t = 0; t < 8; t++) {
            uint32_t tb = ebase + (uint32_t)t * 1024;
            uint32_t b0, b1, b2, b3, b4, b5, b6, b7;
            ldmatrix_x4(b0, b1, b2, b3, tb + seg1);
            ldmatrix_x4(b4, b5, b6, b7, tb + seg2);
            uint32_t c0 = 0, c1 = 0;       // single chained accumulator pair
            mma16816h(c0, c1, a[0][0], a[0][1], a[0][2], a[0][3], b0, b1);
            mma16816h(c0, c1, a[1][0], a[1][1], a[1][2], a[1][3], b2, b3);
            mma16816h(c0, c1, a[2][0], a[2][1], a[2][2], a[2][3], b4, b5);
            mma16816h(c0, c1, a[3][0], a[3][1], a[3][2], a[3][3], b6, b7);
            acc_a[t] = u2h(c0);
            acc_b[t] = u2h(c1);
        }

        // per-row chunk max; pack both row groups into one half2 for shfl
        __half2 hm0 = acc_a[0], hm1 = acc_b[0];
#pragma unroll
        for (int t = 1; t < 8; t++) {
            hm0 = __hmax2(hm0, acc_a[t]);
            hm1 = __hmax2(hm1, acc_b[t]);
        }
        __half2 mp = __halves2half2(__hmax(__low2half(hm0), __high2half(hm0)),
                                    __hmax(__low2half(hm1), __high2half(hm1)));
        {
            uint32_t mpu = reinterpret_cast<uint32_t&>(mp);
            uint32_t o1 = __shfl_xor_sync(0xffffffffu, mpu, 1);
            mp = __hmax2(mp, u2h(o1));
            mpu = reinterpret_cast<uint32_t&>(mp);
            uint32_t o2 = __shfl_xor_sync(0xffffffffu, mpu, 2);
            mp = __hmax2(mp, u2h(o2));
        }
        float m0 = __low2float(mp), m1 = __high2float(mp);
        run0 = fmaxf(run0, m0);
        run1 = fmaxf(run1, m1);
        float thr0f = run0 - HMARGIN, thr1f = run1 - HMARGIN;

        bool anyc = (m0 >= thr0f) || (m1 >= thr1f);
        buf++; if (buf == 3) buf = 0;
        if (!__any_sync(0xffffffffu, anyc)) continue;

        // stage accs to smem (conflict-free: idx*512 + tid*4)
#pragma unroll
        for (int t = 0; t < 8; t++) {
            asm volatile("st.shared.b32 [%0], %1;" ::
                "r"(stg + (uint32_t)t * 512), "r"(reinterpret_cast<uint32_t&>(acc_a[t])) : "memory");
            asm volatile("st.shared.b32 [%0], %1;" ::
                "r"(stg + (uint32_t)(8 + t) * 512), "r"(reinterpret_cast<uint32_t&>(acc_b[t])) : "memory");
        }

        // half-domain thresholds, biased down so compare is a superset
        __half2 thr0 = __float2half2_rn(thr0f - 2e-5f);
        __half2 thr1 = __float2half2_rn(thr1f - 2e-5f);

        uint32_t mask = 0;
#pragma unroll
        for (int t = 0; t < 8; t++) {
            unsigned ma = __hge2_mask(acc_a[t], thr0);
            unsigned mb = __hge2_mask(acc_b[t], thr1);
            mask |= ((ma & 1u) | ((ma >> 15) & 2u)) << (2 * t);
            mask |= (((mb & 1u) | ((mb >> 15) & 2u)) << (2 * t)) << 16;
        }

        int cntl = __popc(mask);
        int pos = 0;
        if (cntl) pos = atomicAdd(&g_cnt, cntl);   // L2 aggregates same-address warp atomics

        int j0 = (cbase + c) * CHC + q * 2;
        while (mask) {
            int bi = __ffs(mask) - 1;
            mask &= mask - 1;
            int grp = bi >> 4;                 // 0 = rows_a, 1 = rows_b
            int t = (bi & 15) >> 1;
            int odd = bi & 1;
            uint32_t v;
            asm volatile("ld.shared.b32 %0, [%1];" : "=r"(v)
                         : "r"(stg + (uint32_t)(grp * 8 + t) * 512));
            uint32_t hb = odd ? (v >> 16) : (v & 0xFFFFu);
            int row = grp ? row_b : row_a;
            int j = j0 + t * 8 + odd;
            if (pos < CAP) g_cand[pos] = pkcand(row, j, hb);
            pos++;
        }
    }

    // publish per-row final max (both code halves combine here)
    if ((lane & 3) == 0) {
        atomicMax(&g_rowmax[row_a], fenc(run0));
        atomicMax(&g_rowmax[row_b], fenc(run1));
    }
}

// ---------------------------------------------------------------------------
// Exact recheck: pre-filter candidates against per-row FINAL max, then
// reference-matching fp32 d (ascending x,y,z,w FMA chain).
// ---------------------------------------------------------------------------
__global__ void vq_exact(const float* __restrict__ emb) {
    int cnt = g_cnt;
    if (cnt > CAP) cnt = CAP;
    for (int i = blockIdx.x * blockDim.x + threadIdx.x; i < cnt; i += gridDim.x * blockDim.x) {
        unsigned long long u = g_cand[i];
        int n = (int)((u >> 13) & 0x7FFFu);
        int j = (int)(u & 8191u);
        float dotf = __half2float(__ushort_as_half((unsigned short)(u >> 32)));
        float fm = fdec(g_rowmax[n]);
        if (dotf < fm - HMARGIN - 2e-5f) continue;   // obsolete candidate

        const float4* zr = (const float4*)(g_zT + n * DIM);
        const float4* er = (const float4*)(emb + j * DIM);
        float dot = 0.f;
#pragma unroll
        for (int cc = 0; cc < 16; cc++) {
            float4 av = zr[cc];
            float4 bv = er[cc];
            dot = __fmaf_rn(av.x, bv.x, dot);
            dot = __fmaf_rn(av.y, bv.y, dot);
            dot = __fmaf_rn(av.z, bv.z, dot);
            dot = __fmaf_rn(av.w, bv.w, dot);
        }
        float d = __fsub_rn(__fadd_rn(g_A[n], g_B[j]), __fmul_rn(2.0f, dot));
        unsigned long long key = ((unsigned long long)__float_as_uint(d) << 13) | (unsigned)j;
        atomicMin(&g_key[n], key);
    }
}

// ---------------------------------------------------------------------------
// Output: z_q straight-through + idx (decoded from g_key) + loss partials
// ---------------------------------------------------------------------------
__global__ void vq_out(const float* __restrict__ z, const float* __restrict__ emb,
                       float* __restrict__ outF) {
    int t = blockIdx.x * 1024 + threadIdx.x;
    int c = (t >> 12) & 63;
    int n = ((t >> 18) << 12) | (t & 4095);
    int idx = (int)(g_key[n] & 8191ull);
    if (c == 0) outF[1 + NELEM + n] = (float)idx;
    float zv = z[t];
    float e = emb[idx * 64 + c];
    float d1 = __fsub_rn(e, zv);
    outF[1 + t] = __fadd_rn(zv, d1);
    double s = (double)__fmul_rn(d1, d1);
#pragma unroll
    for (int o = 16; o; o >>= 1) s += __shfl_down_sync(0xffffffffu, s, o);
    __shared__ double ws[32];
    int lane = threadIdx.x & 31, w = threadIdx.x >> 5;
    if (lane == 0) ws[w] = s;
    __syncthreads();
    if (w == 0) {
        double v = ws[lane];
#pragma unroll
        for (int o = 16; o; o >>= 1) v += __shfl_down_sync(0xffffffffu, v, o);
        if (lane == 0) g_partial[blockIdx.x] = v;
    }
}

__global__ void vq_loss(float* __restrict__ outF) {
    __shared__ double sh[256];
    double s = 0.0;
    for (int i = threadIdx.x; i < 2048; i += 256) s += g_partial[i];
    sh[threadIdx.x] = s;
    __syncthreads();
    for (int st = 128; st; st >>= 1) {
        if (threadIdx.x < st) sh[threadIdx.x] += sh[threadIdx.x + st];
        __syncthreads();
    }
    if (threadIdx.x == 0) {
        float m = (float)(sh[0] / (double)NELEM);
        outF[0] = __fadd_rn(m, __fmul_rn(0.25f, m));
    }
}

extern "C" void kernel_launch(void* const* d_in, const int* in_sizes, int n_in,
                              void* d_out, int out_size) {
    const float* z = (const float*)d_in[0];
    const float* emb = (const float*)d_in[1];
    float* out = (float*)d_out;

    cudaFuncSetAttribute(vq_mma, cudaFuncAttributeMaxDynamicSharedMemorySize, SMEM_MMA);

    vq_transpose<<<512, 256>>>(z);
    vq_prep<<<2048, 256>>>(emb);
    vq_probe<<<1, 32>>>();                        // spacer: keeps vq_mma in ncu slot
    vq_mma<<<(N_ROWS / 64) * 2, 128, SMEM_MMA>>>();
    vq_exact<<<2048, 256>>>(emb);
    vq_out<<<2048, 1024>>>(z, emb, out);
    vq_loss<<<1, 256>>>(out);
}

// round 16
// speedup vs baseline: 1.9186x; 1.9186x over previous
#include <cuda_runtime.h>
#include <cuda_fp16.h>
#include <cstdint>

#define N_ROWS 32768
#define N_CODES 8192
#define DIM 64
#define HW 4096
#define ZB 262144
#define NELEM 2097152
#define CHC 64               // codes per chunk
#define NCHL 64              // chunks per CTA (one code half = 4096 codes)
#define CAP (1 << 22)
#define HMARGIN 4.5e-4f

__device__ float              g_A[N_ROWS];
__device__ float              g_B[N_CODES];
__device__ float              g_zT[N_ROWS * DIM];
__device__ __half             g_zh[N_ROWS * DIM];
__device__ __half             g_eh[N_CODES * DIM];
__device__ unsigned long long g_key[N_ROWS];
__device__ unsigned int       g_rowmax[N_ROWS];       // order-encoded float max dot
__device__ unsigned long long g_cand[CAP];            // [chunkmax_f16:16]<<32 | [row:15|j:13]
__device__ int                g_cnt;
__device__ double             g_partial[2048];

__device__ __forceinline__ uint32_t smem_u32(const void* p) {
    uint32_t a;
    asm("{ .reg .u64 t; cvta.to.shared.u64 t, %1; cvt.u32.u64 %0, t; }" : "=r"(a) : "l"(p));
    return a;
}
__device__ __forceinline__ void cp_async16(uint32_t dst, const void* src) {
    asm volatile("cp.async.cg.shared.global [%0], [%1], 16;" :: "r"(dst), "l"(src) : "memory");
}
#define CP_COMMIT() asm volatile("cp.async.commit_group;" ::: "memory")
#define CP_WAIT1()  asm volatile("cp.async.wait_group 1;" ::: "memory")
#define CP_WAIT0()  asm volatile("cp.async.wait_group 0;" ::: "memory")

__device__ __forceinline__ void mma16816h(uint32_t& c0, uint32_t& c1,
                                          uint32_t a0, uint32_t a1, uint32_t a2, uint32_t a3,
                                          uint32_t b0, uint32_t b1) {
    asm volatile(
        "mma.sync.aligned.m16n8k16.row.col.f16.f16.f16.f16 "
        "{%0,%1}, {%2,%3,%4,%5}, {%6,%7}, {%0,%1};"
        : "+r"(c0), "+r"(c1)
        : "r"(a0), "r"(a1), "r"(a2), "r"(a3), "r"(b0), "r"(b1));
}
__device__ __forceinline__ void ldmatrix_x4(uint32_t& r0, uint32_t& r1, uint32_t& r2,
                                            uint32_t& r3, uint32_t addr) {
    asm volatile("ldmatrix.sync.aligned.m8n8.x4.shared.b16 {%0,%1,%2,%3}, [%4];"
                 : "=r"(r0), "=r"(r1), "=r"(r2), "=r"(r3) : "r"(addr));
}
__device__ __forceinline__ __half2 u2h(uint32_t v) {
    return reinterpret_cast<__half2&>(v);
}
// monotone float -> unsigned encoding (for atomicMax)
__device__ __forceinline__ unsigned fenc(float f) {
    int b = __float_as_int(f);
    return (b >= 0) ? ((unsigned)b | 0x80000000u) : ~(unsigned)b;
}
__device__ __forceinline__ float fdec(unsigned e) {
    int b = (e & 0x80000000u) ? (int)(e ^ 0x80000000u) : (int)~e;
    return __int_as_float(b);
}
__device__ __forceinline__ unsigned long long pkcand(int row, int j, uint32_t hbits) {
    return ((unsigned long long)hbits << 32) |
           (unsigned long long)(((unsigned)row << 13) | (unsigned)j);
}

// ---------------------------------------------------------------------------
// Transpose z -> zT (f32 row-major), zh (fp16), A = ||z||^2 (ascending-c fma)
// ---------------------------------------------------------------------------
__global__ void vq_transpose(const float* __restrict__ z) {
    __shared__ float sm[64][65];
    int b = blockIdx.x >> 6;
    int hw0 = (blockIdx.x & 63) << 6;
    int cc = threadIdx.x >> 6, hh = threadIdx.x & 63;
    const float* zb = z + b * ZB + hw0;
#pragma unroll
    for (int cq = 0; cq < 16; cq++) {
        int c = cq * 4 + cc;
        sm[hh][c] = zb[c * HW + hh];
    }
    __syncthreads();
#pragma unroll
    for (int rq = 0; rq < 16; rq++) {
        int r = rq * 4 + cc;
        int n = b * 4096 + hw0 + r;
        float v = sm[r][hh];
        g_zT[n * DIM + hh] = v;
        g_zh[n * DIM + hh] = __float2half(v);
    }
    if (threadIdx.x < 64) {
        int r = threadIdx.x;
        float s = 0.f;
#pragma unroll
        for (int c = 0; c < DIM; c++) s = __fmaf_rn(sm[r][c], sm[r][c], s);
        g_A[b * 4096 + hw0 + r] = s;
    }
}

__global__ void vq_prep(const float* __restrict__ emb) {
    int t = blockIdx.x * blockDim.x + threadIdx.x;
    if (t < N_CODES * DIM) g_eh[t] = __float2half(emb[t]);
    if (t < N_ROWS) {
        g_key[t] = 0xFFFFFFFFFFFFFFFFull;
        g_rowmax[t] = 0u;
    }
    if (t == 0) g_cnt = 0;
    if (t < N_CODES) {
        const float4* ep = (const float4*)(emb + t * DIM);
        float s = 0.f;
#pragma unroll
        for (int i = 0; i < 16; i++) {
            float4 v = ep[i];
            s = __fmaf_rn(v.x, v.x, s);
            s = __fmaf_rn(v.y, v.y, s);
            s = __fmaf_rn(v.z, v.z, s);
            s = __fmaf_rn(v.w, v.w, s);
        }
        g_B[t] = s;
    }
}

// no-op spacer so vq_mma lands in the ncu-captured (4th) launch slot
__global__ void vq_probe(void) {}

// ---------------------------------------------------------------------------
// Filter: fp16 mma.sync + per-(row,code-half) running max.
// 128 thr / 4 warps / 64 rows x 4096 codes, grid 1024.
// Candidate payload = per-chunk row max (warp register, no extraction cost):
// chunkmax >= dot, so the final-max prefilter in vq_exact stays conservative.
// ---------------------------------------------------------------------------
#define SMEM_MMA (3 * CHC * 128)   // 24KB: three 8KB e buffers

__global__ __launch_bounds__(128, 8) void vq_mma(void) {
    extern __shared__ char smc[];
    uint32_t sb = smem_u32(smc);
    int tid = threadIdx.x;
    int lane = tid & 31;
    int wid = tid >> 5;                   // 4 warps
    int row0 = (blockIdx.x >> 1) * 64;
    int cbase = (blockIdx.x & 1) * NCHL;  // code half: global chunk offset
    int g = lane >> 2, q = lane & 3;

    int rw = row0 + wid * 16;
    int row_a = rw + g, row_b = row_a + 8;
    uint32_t a[4][4];
#pragma unroll
    for (int ks = 0; ks < 4; ks++) {
        const char* pa = (const char*)(g_zh + row_a * DIM + ks * 16 + q * 2);
        const char* pb = (const char*)(g_zh + row_b * DIM + ks * 16 + q * 2);
        a[ks][0] = *(const uint32_t*)pa;
        a[ks][1] = *(const uint32_t*)pb;
        a[ks][2] = *(const uint32_t*)(pa + 16);
        a[ks][3] = *(const uint32_t*)(pb + 16);
    }

    uint32_t r8 = (uint32_t)(lane & 7);
    uint32_t h2 = (uint32_t)(lane >> 3);
    uint32_t seg1 = (h2 ^ r8) * 16;
    uint32_t seg2 = ((4 + h2) ^ r8) * 16;
    uint32_t lrow = r8 * 128;

    // prefetch chunks 0,1 (512 16B segs each; 128 thr x 4)
#pragma unroll
    for (int pc = 0; pc < 2; pc++) {
#pragma unroll
        for (int i = 0; i < 4; i++) {
            int s = tid + i * 128;
            int r = s >> 3, seg = s & 7;
            uint32_t off = (uint32_t)(r * 128 + seg * 16);
            uint32_t dst = sb + pc * 8192 + (off ^ ((off >> 3) & 0x70));
            cp_async16(dst, g_eh + ((cbase + pc) * CHC + r) * DIM + seg * 8);
        }
        CP_COMMIT();
    }

    const float NEGINF = -__int_as_float(0x7f800000);
    float run0 = NEGINF, run1 = NEGINF;

    int buf = 0;                 // buf = c % 3
    for (int c = 0; c < NCHL; c++) {
        if (c < NCHL - 1) CP_WAIT1(); else CP_WAIT0();
        __syncthreads();         // chunk c ready; chunk c-1's buffer now free

        uint32_t ebase = sb + (uint32_t)buf * 8192 + lrow;

        // prefetch c+2 into buffer (c+2)%3 == (c-1)%3
        if (c + 2 < NCHL) {
            int pbuf = buf - 1; if (pbuf < 0) pbuf = 2;
#pragma unroll
            for (int i = 0; i < 4; i++) {
                int s = tid + i * 128;
                int r = s >> 3, seg = s & 7;
                uint32_t off = (uint32_t)(r * 128 + seg * 16);
                uint32_t dst = sb + (uint32_t)pbuf * 8192 + (off ^ ((off >> 3) & 0x70));
                cp_async16(dst, g_eh + ((cbase + c + 2) * CHC + r) * DIM + seg * 8);
            }
            CP_COMMIT();
        }

        __half2 acc_a[8], acc_b[8];
#pragma unroll
        for (int t = 0; t < 8; t++) {
            uint32_t tb = ebase + (uint32_t)t * 1024;
            uint32_t b0, b1, b2, b3, b4, b5, b6, b7;
            ldmatrix_x4(b0, b1, b2, b3, tb + seg1);
            ldmatrix_x4(b4, b5, b6, b7, tb + seg2);
            uint32_t c0 = 0, c1 = 0;       // single chained accumulator pair
            mma16816h(c0, c1, a[0][0], a[0][1], a[0][2], a[0][3], b0, b1);
            mma16816h(c0, c1, a[1][0], a[1][1], a[1][2], a[1][3], b2, b3);
            mma16816h(c0, c1, a[2][0], a[2][1], a[2][2], a[2][3], b4, b5);
            mma16816h(c0, c1, a[3][0], a[3][1], a[3][2], a[3][3], b6, b7);
            acc_a[t] = u2h(c0);
            acc_b[t] = u2h(c1);
        }

        // per-row chunk max; pack both row groups into one half2 for shfl
        __half2 hm0 = acc_a[0], hm1 = acc_b[0];
#pragma unroll
        for (int t = 1; t < 8; t++) {
            hm0 = __hmax2(hm0, acc_a[t]);
            hm1 = __hmax2(hm1, acc_b[t]);
        }
        __half2 mp = __halves2half2(__hmax(__low2half(hm0), __high2half(hm0)),
                                    __hmax(__low2half(hm1), __high2half(hm1)));
        {
            uint32_t mpu = reinterpret_cast<uint32_t&>(mp);
            uint32_t o1 = __shfl_xor_sync(0xffffffffu, mpu, 1);
            mp = __hmax2(mp, u2h(o1));
            mpu = reinterpret_cast<uint32_t&>(mp);
            uint32_t o2 = __shfl_xor_sync(0xffffffffu, mpu, 2);
            mp = __hmax2(mp, u2h(o2));
        }
        float m0 = __low2float(mp), m1 = __high2float(mp);
        run0 = fmaxf(run0, m0);
        run1 = fmaxf(run1, m1);
        float thr0f = run0 - HMARGIN, thr1f = run1 - HMARGIN;

        bool anyc = (m0 >= thr0f) || (m1 >= thr1f);
        buf++; if (buf == 3) buf = 0;
        if (!__any_sync(0xffffffffu, anyc)) continue;

        // chunk-max payload bits (exact half values already)
        uint32_t mpu = reinterpret_cast<uint32_t&>(mp);
        uint32_t m0h = mpu & 0xFFFFu;
        uint32_t m1h = mpu >> 16;

        // half-domain thresholds, biased down so compare is a superset
        __half2 thr0 = __float2half2_rn(thr0f - 2e-5f);
        __half2 thr1 = __float2half2_rn(thr1f - 2e-5f);

        uint32_t mask = 0;
#pragma unroll
        for (int t = 0; t < 8; t++) {
            unsigned ma = __hge2_mask(acc_a[t], thr0);
            unsigned mb = __hge2_mask(acc_b[t], thr1);
            mask |= ((ma & 1u) | ((ma >> 15) & 2u)) << (2 * t);
            mask |= (((mb & 1u) | ((mb >> 15) & 2u)) << (2 * t)) << 16;
        }

        int cntl = __popc(mask);
        int pre = cntl;
#pragma unroll
        for (int o = 1; o < 32; o <<= 1) {
            int v = __shfl_up_sync(0xffffffffu, pre, o);
            if (lane >= o) pre += v;
        }
        int total = __shfl_sync(0xffffffffu, pre, 31);
        int base = 0;
        if (lane == 31 && total) base = atomicAdd(&g_cnt, total);
        base = __shfl_sync(0xffffffffu, base, 31);
        int pos = base + pre - cntl;

        int j0 = (cbase + c) * CHC + q * 2;
        while (mask) {
            int bi = __ffs(mask) - 1;
            mask &= mask - 1;
            int grp = bi >> 4;                 // 0 = rows_a, 1 = rows_b
            int row = grp ? row_b : row_a;
            uint32_t hb = grp ? m1h : m0h;
            int j = j0 + ((bi & 15) >> 1) * 8 + (bi & 1);
            if (pos < CAP) g_cand[pos] = pkcand(row, j, hb);
            pos++;
        }
    }

    // publish per-row final max (both code halves combine here)
    if ((lane & 3) == 0) {
        atomicMax(&g_rowmax[row_a], fenc(run0));
        atomicMax(&g_rowmax[row_b], fenc(run1));
    }
}

// ---------------------------------------------------------------------------
// Exact recheck: prefilter on chunk-max payload vs per-row FINAL max, then
// reference-matching fp32 d (ascending x,y,z,w FMA chain).
// ---------------------------------------------------------------------------
__global__ void vq_exact(const float* __restrict__ emb) {
    int cnt = g_cnt;
    if (cnt > CAP) cnt = CAP;
    for (int i = blockIdx.x * blockDim.x + threadIdx.x; i < cnt; i += gridDim.x * blockDim.x) {
        unsigned long long u = g_cand[i];
        int n = (int)((u >> 13) & 0x7FFFu);
        int j = (int)(u & 8191u);
        float cmax = __half2float(__ushort_as_half((unsigned short)(u >> 32)));
        float fm = fdec(g_rowmax[n]);
        if (cmax < fm - HMARGIN - 2e-5f) continue;   // whole chunk obsolete

        const float4* zr = (const float4*)(g_zT + n * DIM);
        const float4* er = (const float4*)(emb + j * DIM);
        float dot = 0.f;
#pragma unroll
        for (int cc = 0; cc < 16; cc++) {
            float4 av = zr[cc];
            float4 bv = er[cc];
            dot = __fmaf_rn(av.x, bv.x, dot);
            dot = __fmaf_rn(av.y, bv.y, dot);
            dot = __fmaf_rn(av.z, bv.z, dot);
            dot = __fmaf_rn(av.w, bv.w, dot);
        }
        float d = __fsub_rn(__fadd_rn(g_A[n], g_B[j]), __fmul_rn(2.0f, dot));
        unsigned long long key = ((unsigned long long)__float_as_uint(d) << 13) | (unsigned)j;
        atomicMin(&g_key[n], key);
    }
}

// ---------------------------------------------------------------------------
// Output: z_q straight-through + idx (decoded from g_key) + loss partials
// ---------------------------------------------------------------------------
__global__ void vq_out(const float* __restrict__ z, const float* __restrict__ emb,
                       float* __restrict__ outF) {
    int t = blockIdx.x * 1024 + threadIdx.x;
    int c = (t >> 12) & 63;
    int n = ((t >> 18) << 12) | (t & 4095);
    int idx = (int)(g_key[n] & 8191ull);
    if (c == 0) outF[1 + NELEM + n] = (float)idx;
    float zv = z[t];
    float e = emb[idx * 64 + c];
    float d1 = __fsub_rn(e, zv);
    outF[1 + t] = __fadd_rn(zv, d1);
    double s = (double)__fmul_rn(d1, d1);
#pragma unroll
    for (int o = 16; o; o >>= 1) s += __shfl_down_sync(0xffffffffu, s, o);
    __shared__ double ws[32];
    int lane = threadIdx.x & 31, w = threadIdx.x >> 5;
    if (lane == 0) ws[w] = s;
    __syncthreads();
    if (w == 0) {
        double v = ws[lane];
#pragma unroll
        for (int o = 16; o; o >>= 1) v += __shfl_down_sync(0xffffffffu, v, o);
        if (lane == 0) g_partial[blockIdx.x] = v;
    }
}

__global__ void vq_loss(float* __restrict__ outF) {
    __shared__ double sh[256];
    double s = 0.0;
    for (int i = threadIdx.x; i < 2048; i += 256) s += g_partial[i];
    sh[threadIdx.x] = s;
    __syncthreads();
    for (int st = 128; st; st >>= 1) {
        if (threadIdx.x < st) sh[threadIdx.x] += sh[threadIdx.x + st];
        __syncthreads();
    }
    if (threadIdx.x == 0) {
        float m = (float)(sh[0] / (double)NELEM);
        outF[0] = __fadd_rn(m, __fmul_rn(0.25f, m));
    }
}

extern "C" void kernel_launch(void* const* d_in, const int* in_sizes, int n_in,
                              void* d_out, int out_size) {
    const float* z = (const float*)d_in[0];
    const float* emb = (const float*)d_in[1];
    float* out = (float*)d_out;

    cudaFuncSetAttribute(vq_mma, cudaFuncAttributeMaxDynamicSharedMemorySize, SMEM_MMA);

    vq_transpose<<<512, 256>>>(z);
    vq_prep<<<2048, 256>>>(emb);
    vq_probe<<<1, 32>>>();                        // spacer: keeps vq_mma in ncu slot
    vq_mma<<<(N_ROWS / 64) * 2, 128, SMEM_MMA>>>();
    vq_exact<<<2048, 256>>>(emb);
    vq_out<<<2048, 1024>>>(z, emb, out);
    vq_loss<<<1, 256>>>(out);
}